// round 16
// baseline (speedup 1.0000x reference)
#include <cuda_runtime.h>
#include <cuda_bf16.h>
#include <math.h>
#include <stdint.h>

// ---------------------------------------------------------------------------
// FABlock2D on GB300. tf32 mma.sync GEMMs, BK=32 cp.async pipeline, ldmatrix
// fragments, reg-capped 256-thread CTAs (16 warps/SM). R16: 3-stage pipeline
// for the 256-thread big GEMMs (2 CTAs x 110.6KB smem = 221KB <= 228KB), so
// two k-tiles are in flight during compute. einsum2/duals stay 2-stage.
// ---------------------------------------------------------------------------

#define NB   4
#define NGR  128
#define DIMC 256
#define HEADS 8
#define DH   64
#define ROWS_ALL (NB*NGR*NGR)   // 65536

// ------------------------- scratch (device globals) ------------------------
#define UN_OFF    0L
#define VT_OFF    50331648L
#define UPHI_OFF  0L
#define GN_OFF    33554432L
#define U2_OFF    0L
#define LN2_OFF   16777216L
#define HID_OFF   33554432L
#define ARENA_ELEMS 100663296L

__device__ float g_arena[ARENA_ELEMS];
__device__ float g_meanx[512*256];
__device__ float g_meany[512*256];
__device__ float g_p2   [2*512*256];
__device__ float g_hsm2 [2*512*1024];
__device__ float g_ux   [512*256];
__device__ float g_uy   [512*256];
__device__ float g_qk2  [2*512*1024];
__device__ float g_q2   [2*262144];
__device__ float g_k2   [2*262144];
__device__ float g_att2 [2*524288];   // [0]=x (kx), [1]=y (ky)

// tf32-rounded TRANSPOSED weight copies [N][K]
#define W_XIN  0L
#define W_YIN  65536L
#define W_X1   131072L
#define W_Y1   393216L
#define W_X2   655360L
#define W_Y2   917504L
#define W_QKX  1179648L
#define W_QKY  1441792L
#define W_V    1703936L
#define W_M    1835008L
#define W_F1   1966080L
#define W_F2   2228224L
#define W_TOTAL 2490368L
__device__ float g_wr[W_TOTAL];

// ------------------------------- helpers -----------------------------------
__device__ __forceinline__ float gelu_tanh(float x) {
    float x3 = x * x * x;
    return 0.5f * x * (1.0f + tanhf(0.7978845608028654f * (x + 0.044715f * x3)));
}
__device__ __forceinline__ uint32_t f2tf32(float x) {
    uint32_t r;
    asm("cvt.rna.tf32.f32 %0, %1;" : "=r"(r) : "f"(x));
    return r;
}
__device__ __forceinline__ float tf32r(float x) { return __uint_as_float(f2tf32(x)); }
__device__ __forceinline__ void mma_tf32(float c[4], const uint32_t a[4], const uint32_t b[2]) {
    asm volatile(
        "mma.sync.aligned.m16n8k8.row.col.f32.tf32.tf32.f32 "
        "{%0,%1,%2,%3}, {%4,%5,%6,%7}, {%8,%9}, {%0,%1,%2,%3};\n"
        : "+f"(c[0]), "+f"(c[1]), "+f"(c[2]), "+f"(c[3])
        : "r"(a[0]), "r"(a[1]), "r"(a[2]), "r"(a[3]), "r"(b[0]), "r"(b[1]));
}
__device__ __forceinline__ void cp16(void* dst, const void* src) {
    uint32_t d = (uint32_t)__cvta_generic_to_shared(dst);
    asm volatile("cp.async.ca.shared.global [%0], [%1], 16;\n" :: "r"(d), "l"(src));
}
__device__ __forceinline__ void ldsm4(uint32_t& r0, uint32_t& r1, uint32_t& r2, uint32_t& r3,
                                      uint32_t addr) {
    asm volatile("ldmatrix.sync.aligned.m8n8.x4.shared.b16 {%0,%1,%2,%3}, [%4];"
                 : "=r"(r0), "=r"(r1), "=r"(r2), "=r"(r3) : "r"(addr));
}

// ------------------- weight round+transpose prep (one launch) ---------------
__global__ void round_weights_kernel(
        const float* __restrict__ wxin, const float* __restrict__ wyin,
        const float* __restrict__ wx1,  const float* __restrict__ wy1,
        const float* __restrict__ wx2,  const float* __restrict__ wy2,
        const float* __restrict__ wqkx, const float* __restrict__ wqky,
        const float* __restrict__ wv,   const float* __restrict__ wm,
        const float* __restrict__ wf1,  const float* __restrict__ wf2,
        float* __restrict__ dst) {
    long i = (long)blockIdx.x * 256 + threadIdx.x;
    if (i >= W_TOTAL) return;
    const float* src; long off; int K, N;
    if      (i < W_YIN) { src = wxin; off = W_XIN; K = 256;  N = 256; }
    else if (i < W_X1)  { src = wyin; off = W_YIN; K = 256;  N = 256; }
    else if (i < W_Y1)  { src = wx1;  off = W_X1;  K = 256;  N = 1024; }
    else if (i < W_X2)  { src = wy1;  off = W_Y1;  K = 256;  N = 1024; }
    else if (i < W_Y2)  { src = wx2;  off = W_X2;  K = 1024; N = 256; }
    else if (i < W_QKX) { src = wy2;  off = W_Y2;  K = 1024; N = 256; }
    else if (i < W_QKY) { src = wqkx; off = W_QKX; K = 256;  N = 1024; }
    else if (i < W_V)   { src = wqky; off = W_QKY; K = 256;  N = 1024; }
    else if (i < W_M)   { src = wv;   off = W_V;   K = 256;  N = 512; }
    else if (i < W_F1)  { src = wm;   off = W_M;   K = 512;  N = 256; }
    else if (i < W_F2)  { src = wf1;  off = W_F1;  K = 256;  N = 1024; }
    else                { src = wf2;  off = W_F2;  K = 1024; N = 256; }
    long l = i - off;
    int n = (int)(l / K), k = (int)(l % K);
    dst[i] = tf32r(src[(long)k * N + n]);
}

// --------------------- pipelined tf32 tensor-core GEMM ----------------------
template<int BM, int BN, int BK, int BLDSM, int STAGES>
struct GemmSmem {
    float As[STAGES][BM][BK + 4];
    float Bs[STAGES][BLDSM ? BN : BK][BLDSM ? (BK + 4) : (BN + 8)];
};

template<int BM, int BN, int BK, int THREADS, int WARPS_M, int WARPS_N, int EPI, int BLDSM,
         int STAGES>
__device__ __forceinline__ void gemm_core(
        const float* __restrict__ A, const float* __restrict__ B, float* __restrict__ C,
        int M, int N, int K, int zb,
        const float* __restrict__ bias, const float* __restrict__ res,
        int do_gelu, int round_out,
        GemmSmem<BM, BN, BK, BLDSM, STAGES>& sm) {
    constexpr int WM = BM / WARPS_M;
    constexpr int WN = BN / WARPS_N;
    constexpr int MI = WM / 16;
    constexpr int NI = WN / 8;
    constexpr int ITA = (BM * BK / 4) / THREADS;
    constexpr int ITB = (BK * BN / 4) / THREADS;
    constexpr int ASTRIDE = BK + 4;
    constexpr int BSTRIDE = BLDSM ? (BK + 4) : (BN + 8);
    constexpr int A_STG = BM * ASTRIDE;
    constexpr int B_STG = (BLDSM ? BN : BK) * BSTRIDE;

    int tid = threadIdx.x;
    int warp = tid >> 5, lane = tid & 31;
    int wm = warp / WARPS_N, wn = warp % WARPS_N;
    int m0 = blockIdx.y * BM, n0 = blockIdx.x * BN;
    int lg = lane >> 2, lt = lane & 3;
    int lrow = lane & 7, lsel = lane >> 3;

    float c[MI][NI][4] = {};

    auto load_stage = [&](int k0, int s) {
        #pragma unroll
        for (int it = 0; it < ITA; it++) {
            int v = tid + it * THREADS;
            int m = v / (BK / 4), kq = (v % (BK / 4)) * 4;
            cp16(&sm.As[s][m][kq], A + (long)(m0 + m) * K + k0 + kq);
        }
        if (BLDSM) {
            #pragma unroll
            for (int it = 0; it < ITB; it++) {
                int v = tid + it * THREADS;
                int n = v / (BK / 4), kq = (v % (BK / 4)) * 4;
                cp16(&sm.Bs[s][n][kq], B + (long)(n0 + n) * K + k0 + kq);
            }
        } else {
            #pragma unroll
            for (int it = 0; it < ITB; it++) {
                int v = tid + it * THREADS;
                int k = v / (BN / 4), nq = (v % (BN / 4)) * 4;
                cp16(&sm.Bs[s][k][nq], B + (long)(k0 + k) * N + n0 + nq);
            }
        }
    };

    uint32_t As_sm = (uint32_t)__cvta_generic_to_shared(&sm.As[0][0][0]);
    uint32_t Bs_sm = (uint32_t)__cvta_generic_to_shared(&sm.Bs[0][0][0]);
    uint32_t a_off = ((uint32_t)(wm * WM + (lsel & 1) * 8 + lrow) * ASTRIDE
                      + (uint32_t)(lsel >> 1) * 4) * 4u;
    uint32_t b_off = 0;
    if (BLDSM)
        b_off = ((uint32_t)(wn * WN + (lsel >> 1) * 8 + lrow) * BSTRIDE
                 + (uint32_t)(lsel & 1) * 4) * 4u;

    int T = K / BK;
    #pragma unroll
    for (int s = 0; s < STAGES - 1; s++) {
        load_stage(s * BK, s);
        asm volatile("cp.async.commit_group;\n");
    }
    int cur = 0;              // compute slot
    int ld = STAGES - 1;      // load slot
    for (int t = 0; t < T; t++) {
        // load stage t+STAGES-1 into slot ld (protected by end-of-iter sync of t-1)
        if (t + STAGES - 1 < T) load_stage((t + STAGES - 1) * BK, ld);
        asm volatile("cp.async.commit_group;\n");
        asm volatile("cp.async.wait_group %0;\n" :: "n"(STAGES - 1));
        __syncthreads();
        uint32_t a_base = As_sm + (uint32_t)(cur * A_STG) * 4u + a_off;
        uint32_t b_base = Bs_sm + (uint32_t)(cur * B_STG) * 4u + b_off;
        #pragma unroll
        for (int ks = 0; ks < BK / 8; ks++) {
            int kb = ks * 8;
            uint32_t af[MI][4], bf[NI][2];
            #pragma unroll
            for (int mi = 0; mi < MI; mi++)
                ldsm4(af[mi][0], af[mi][1], af[mi][2], af[mi][3],
                      a_base + ((uint32_t)(mi * 16 * ASTRIDE + kb)) * 4u);
            if (BLDSM) {
                #pragma unroll
                for (int ni = 0; ni < NI; ni += 2)
                    ldsm4(bf[ni][0], bf[ni][1], bf[ni + 1][0], bf[ni + 1][1],
                          b_base + ((uint32_t)(ni * 8 * BSTRIDE + kb)) * 4u);
            } else {
                #pragma unroll
                for (int ni = 0; ni < NI; ni++) {
                    int nc = wn * WN + ni * 8 + lg;
                    bf[ni][0] = __float_as_uint(sm.Bs[cur][kb + lt][nc]);
                    bf[ni][1] = __float_as_uint(sm.Bs[cur][kb + lt + 4][nc]);
                }
            }
            #pragma unroll
            for (int mi = 0; mi < MI; mi++)
                #pragma unroll
                for (int ni = 0; ni < NI; ni++)
                    mma_tf32(c[mi][ni], af[mi], bf[ni]);
        }
        __syncthreads();
        cur = (cur == STAGES - 1) ? 0 : cur + 1;
        ld  = (ld  == STAGES - 1) ? 0 : ld + 1;
    }

    if (EPI == 3) {
        // GroupNorm epilogue (requires WN == 64: one c-group per warp).
        int b = zb >> 3, h = zb & 7;
        int i_idx = (n0 + wn * WN) >> 6;
        #pragma unroll
        for (int mi = 0; mi < MI; mi++) {
            #pragma unroll
            for (int half = 0; half < 2; half++) {
                float s = 0.f, s2 = 0.f;
                #pragma unroll
                for (int ni = 0; ni < NI; ni++) {
                    float v0 = c[mi][ni][half * 2 + 0];
                    float v1 = c[mi][ni][half * 2 + 1];
                    s += v0 + v1; s2 += v0 * v0 + v1 * v1;
                }
                s  += __shfl_xor_sync(0xffffffffu, s, 1);
                s  += __shfl_xor_sync(0xffffffffu, s, 2);
                s2 += __shfl_xor_sync(0xffffffffu, s2, 1);
                s2 += __shfl_xor_sync(0xffffffffu, s2, 2);
                float mean = s * (1.f / 64.f);
                float var = fmaxf(s2 * (1.f / 64.f) - mean * mean, 0.f);
                float r = rsqrtf(var + 1e-6f);
                int l = wm * WM + mi * 16 + lg + half * 8;
                float* op = C + ((long)((b * 128 + i_idx) * 128 + l)) * 512 + h * 64;
                #pragma unroll
                for (int ni = 0; ni < NI; ni++) {
                    float2 o;
                    o.x = tf32r((c[mi][ni][half * 2 + 0] - mean) * r);
                    o.y = tf32r((c[mi][ni][half * 2 + 1] - mean) * r);
                    *(float2*)(op + ni * 8 + 2 * lt) = o;
                }
            }
        }
        return;
    }
    if (EPI == 2) {
        // einsum1 transpose scatter (generic WN): col -> uphiT[m][(i,c)]
        #pragma unroll
        for (int mi = 0; mi < MI; mi++) {
            #pragma unroll
            for (int half = 0; half < 2; half++) {
                int i_row = m0 + wm * WM + mi * 16 + lg + half * 8;
                #pragma unroll
                for (int ni = 0; ni < NI; ni++) {
                    int col = n0 + wn * WN + ni * 8 + 2 * lt;
                    int m_idx = col >> 6, cc = col & 63;
                    float2 o;
                    o.x = tf32r(c[mi][ni][half * 2 + 0]);
                    o.y = tf32r(c[mi][ni][half * 2 + 1]);
                    *(float2*)(C + (long)m_idx * 8192 + (long)i_row * 64 + cc) = o;
                }
            }
        }
        return;
    }

    #pragma unroll
    for (int mi = 0; mi < MI; mi++) {
        #pragma unroll
        for (int ni = 0; ni < NI; ni++) {
            int col = n0 + wn * WN + ni * 8 + 2 * lt;
            float b0 = 0.f, b1 = 0.f;
            if (EPI == 0 && bias) { b0 = bias[col]; b1 = bias[col + 1]; }
            #pragma unroll
            for (int half = 0; half < 2; half++) {
                long row = m0 + wm * WM + mi * 16 + lg + half * 8;
                float v0 = c[mi][ni][half * 2 + 0] + b0;
                float v1 = c[mi][ni][half * 2 + 1] + b1;
                if (EPI == 0 && do_gelu) { v0 = gelu_tanh(v0); v1 = gelu_tanh(v1); }
                if (EPI == 0 && res) {
                    v0 += res[row * (long)N + col];
                    v1 += res[row * (long)N + col + 1];
                }
                if (EPI == 0 && round_out) { v0 = tf32r(v0); v1 = tf32r(v1); }
                if (EPI == 1) { v0 = tf32r(v0); v1 = tf32r(v1); }
                float2 o; o.x = v0; o.y = v1;
                if (EPI == 1) {
                    int bb = (int)(row >> 14), y = (int)(row >> 7) & 127, x = (int)row & 127;
                    int h = col >> 6, cc = col & 63;
                    long off = ((long)((bb * 8 + h) * 128 + y)) * 8192 + x * 64 + cc;
                    *(float2*)(C + off) = o;
                } else {
                    *(float2*)(C + row * (long)N + col) = o;
                }
            }
        }
    }
}

// MINB enforces the reg budget (256thr, MINB=2 -> 128-reg cap -> 16 warps/SM).
template<int BM, int BN, int BK, int THREADS, int WARPS_M, int WARPS_N, int EPI, int BLDSM,
         int MINB, int STAGES>
__global__ __launch_bounds__(THREADS, MINB) void gemm_pipe_kernel(
        const float* __restrict__ A, const float* __restrict__ B, float* __restrict__ C,
        int M, int N, int K, long sA, long sB, long sC,
        const float* __restrict__ bias, const float* __restrict__ res,
        int do_gelu, int round_out) {
    extern __shared__ __align__(16) float dsm[];
    auto& sm = *reinterpret_cast<GemmSmem<BM, BN, BK, BLDSM, STAGES>*>(dsm);
    gemm_core<BM, BN, BK, THREADS, WARPS_M, WARPS_N, EPI, BLDSM, STAGES>(
        A + (long)blockIdx.z * sA, B + (long)blockIdx.z * sB, C + (long)blockIdx.z * sC,
        M, N, K, blockIdx.z, bias, res, do_gelu, round_out, sm);
}

template<int BM, int BN, int BK, int THREADS, int WARPS_M, int WARPS_N>
__global__ __launch_bounds__(THREADS) void gemm_dual_kernel(
        const float* __restrict__ A0, const float* __restrict__ A1,
        const float* __restrict__ B0, const float* __restrict__ B1,
        float* __restrict__ C0, float* __restrict__ C1,
        int M, int N, int K,
        const float* __restrict__ bias0, const float* __restrict__ bias1,
        int do_gelu, int round_out) {
    __shared__ __align__(16) GemmSmem<BM, BN, BK, 1, 2> sm;
    bool z = blockIdx.z != 0;
    gemm_core<BM, BN, BK, THREADS, WARPS_M, WARPS_N, 0, 1, 2>(
        z ? A1 : A0, z ? B1 : B0, z ? C1 : C0, M, N, K, 0,
        z ? bias1 : bias0, nullptr, do_gelu, round_out, sm);
}

#define BIG3_SMEM_W  (int)sizeof(GemmSmem<128,128,32,1,3>)   // 110592 B
#define BIG3_SMEM_E  (int)sizeof(GemmSmem<128,128,32,0,3>)   // 107520 B
#define BIG2_SMEM_E  (int)sizeof(GemmSmem<128,128,32,0,2>)   // ~71.7KB

// ----------------------- LayerNorm: warp per row ----------------------------
__global__ void ln8_kernel(const float* __restrict__ x, const float* __restrict__ g,
                           const float* __restrict__ b, float* __restrict__ y, float eps) {
    long row = (long)blockIdx.x * 8 + (threadIdx.x >> 5);
    int lane = threadIdx.x & 31;
    const float* xp = x + row * 256 + lane * 8;
    float4 a = *(const float4*)xp;
    float4 c4 = *(const float4*)(xp + 4);
    float s  = a.x + a.y + a.z + a.w + c4.x + c4.y + c4.z + c4.w;
    float s2 = a.x*a.x + a.y*a.y + a.z*a.z + a.w*a.w
             + c4.x*c4.x + c4.y*c4.y + c4.z*c4.z + c4.w*c4.w;
    #pragma unroll
    for (int o = 16; o; o >>= 1) {
        s  += __shfl_xor_sync(0xffffffffu, s,  o);
        s2 += __shfl_xor_sync(0xffffffffu, s2, o);
    }
    float mean = s * (1.f / 256.f);
    float var  = s2 * (1.f / 256.f) - mean * mean;
    float r = rsqrtf(var + eps);
    const float* gp = g + lane * 8;
    const float* bp = b + lane * 8;
    float* op = y + row * 256 + lane * 8;
    float4 o0, o1;
    o0.x = tf32r((a.x  - mean) * r * gp[0] + bp[0]);
    o0.y = tf32r((a.y  - mean) * r * gp[1] + bp[1]);
    o0.z = tf32r((a.z  - mean) * r * gp[2] + bp[2]);
    o0.w = tf32r((a.w  - mean) * r * gp[3] + bp[3]);
    o1.x = tf32r((c4.x - mean) * r * gp[4] + bp[4]);
    o1.y = tf32r((c4.y - mean) * r * gp[5] + bp[5]);
    o1.z = tf32r((c4.z - mean) * r * gp[6] + bp[6]);
    o1.w = tf32r((c4.w - mean) * r * gp[7] + bp[7]);
    *(float4*)op = o0;
    *(float4*)(op + 4) = o1;
}

// ------------------------- means over x / over y ----------------------------
__global__ void mean_over_x_kernel(const float* __restrict__ un, float* __restrict__ out) {
    int by = blockIdx.x;
    int c = threadIdx.x;
    const float* base = un + (long)by * NGR * DIMC + c;
    float s = 0.f;
    #pragma unroll 4
    for (int x = 0; x < NGR; x++) s += base[(long)x * DIMC];
    out[(long)by * DIMC + c] = tf32r(s * (1.f / (float)NGR));
}
__global__ void mean_over_y_kernel(const float* __restrict__ un, float* __restrict__ out) {
    int bx = blockIdx.x;
    int b = bx >> 7, x = bx & 127;
    int c = threadIdx.x;
    const float* base = un + ((long)b * NGR * NGR + x) * DIMC + c;
    float s = 0.f;
    #pragma unroll 4
    for (int y = 0; y < NGR; y++) s += base[(long)y * NGR * DIMC];
    out[(long)bx * DIMC + c] = tf32r(s * (1.f / (float)NGR));
}

// ------------------------------ RoPE (x+y) ----------------------------------
__global__ void rope2_kernel(const float* __restrict__ qk2,
                             const float* __restrict__ cx, const float* __restrict__ sx,
                             const float* __restrict__ cy, const float* __restrict__ sy,
                             float* __restrict__ q2, float* __restrict__ k2) {
    int idx = blockIdx.x * 256 + threadIdx.x;
    int z = idx >> 18;
    int i = idx & 262143;
    int d = i & 63;
    int n = (i >> 6) & 127;
    int h = (i >> 13) & 7;
    int b = i >> 16;
    const float* P = qk2 + (long)z * 524288 + (long)(b * 128 + n) * 1024;
    const float* cosv = z ? cy : cx;
    const float* sinv = z ? sy : sx;
    float c = cosv[n * 64 + d], s = sinv[n * 64 + d];
    int col = h * 64 + d;
    float t  = P[col];
    float rt = (d < 32) ? -P[col + 32] : P[col - 32];
    q2[idx] = t * c + rt * s;
    float t2  = P[512 + col];
    float rt2 = (d < 32) ? -P[512 + col + 32] : P[512 + col - 32];
    k2[idx] = t2 * c + rt2 * s;
}

// ----------------------- attention scores + softmax -------------------------
__global__ void attn_kernel(const float* __restrict__ q, const float* __restrict__ k,
                            float* __restrict__ attn) {
    __shared__ float qT[64 * 32];
    __shared__ float kT[64 * 128];
    int bh = blockIdx.x;
    int quarter = blockIdx.y;
    const float* qb = q + (long)bh * 8192 + quarter * 2048;
    const float* kb = k + (long)bh * 8192;
    int tid = threadIdx.x;
    for (int t = tid; t < 8192; t += 256) {
        int n = t >> 6, d = t & 63;
        kT[d * 128 + n] = kb[t];
    }
    for (int t = tid; t < 2048; t += 256) {
        int n = t >> 6, d = t & 63;
        qT[d * 32 + n] = qb[t];
    }
    __syncthreads();
    int r = tid >> 3;
    int c0 = (tid & 7) * 2;
    float acc[16] = {};
    #pragma unroll 8
    for (int d = 0; d < 64; d++) {
        float qv = qT[d * 32 + r];
        #pragma unroll
        for (int j = 0; j < 8; j++) {
            acc[2 * j]     += qv * kT[d * 128 + c0 + 16 * j];
            acc[2 * j + 1] += qv * kT[d * 128 + c0 + 1 + 16 * j];
        }
    }
    float mx = -1e30f;
    #pragma unroll
    for (int j = 0; j < 16; j++) { acc[j] *= (1.f / 64.f); mx = fmaxf(mx, acc[j]); }
    #pragma unroll
    for (int o = 1; o < 8; o <<= 1) mx = fmaxf(mx, __shfl_xor_sync(0xffffffffu, mx, o));
    float s = 0.f;
    #pragma unroll
    for (int j = 0; j < 16; j++) { acc[j] = __expf(acc[j] - mx); s += acc[j]; }
    #pragma unroll
    for (int o = 1; o < 8; o <<= 1) s += __shfl_xor_sync(0xffffffffu, s, o);
    float inv = 1.f / s;
    float* op = attn + (long)bh * 16384 + (long)(quarter * 32 + r) * 128;
    #pragma unroll
    for (int j = 0; j < 8; j++) {
        float2 o;
        o.x = tf32r(acc[2 * j] * inv);
        o.y = tf32r(acc[2 * j + 1] * inv);
        *(float2*)(op + c0 + 16 * j) = o;
    }
}

// ------------------------------- host side ----------------------------------
// Big EPI=0/1 GEMMs: 256 threads, 2x4 warps, MINB=2, 3-stage.
static inline void gemm_big(const float* A, const float* Bt, float* C,
                            int M, int N, int K,
                            const float* bias, const float* res, int do_gelu, int round_out) {
    dim3 grid(N / 128, M / 128, 1);
    gemm_pipe_kernel<128, 128, 32, 256, 2, 4, 0, 1, 2, 3><<<grid, 256, BIG3_SMEM_W>>>(
        A, Bt, C, M, N, K, 0, 0, 0, bias, res, do_gelu, round_out);
}
static inline void gemm_wv(const float* A, const float* Bt, float* C,
                           int M, int N, int K) {
    dim3 grid(N / 128, M / 128, 1);
    gemm_pipe_kernel<128, 128, 32, 256, 2, 4, 1, 1, 2, 3><<<grid, 256, BIG3_SMEM_W>>>(
        A, Bt, C, M, N, K, 0, 0, 0, nullptr, nullptr, 0, 0);
}
static inline void gemm_e1(const float* A, const float* B, float* C,
                           int M, int N, int K, long sA, long sB, long sC, int batch) {
    dim3 grid(N / 128, M / 128, batch);
    gemm_pipe_kernel<128, 128, 32, 256, 2, 4, 2, 0, 2, 3><<<grid, 256, BIG3_SMEM_E>>>(
        A, B, C, M, N, K, sA, sB, sC, nullptr, nullptr, 0, 0);
}
// einsum2: 128 threads, 2x2 (GN epilogue needs WN=64), 2-stage, MINB=3.
static inline void gemm_e2(const float* A, const float* B, float* C,
                           int M, int N, int K, long sA, long sB, long sC, int batch) {
    dim3 grid(N / 128, M / 128, batch);
    gemm_pipe_kernel<128, 128, 32, 128, 2, 2, 3, 0, 3, 2><<<grid, 128, BIG2_SMEM_E>>>(
        A, B, C, M, N, K, sA, sB, sC, nullptr, nullptr, 0, 0);
}
static inline void gemm_dual(const float* A0, const float* A1,
                             const float* B0t, const float* B1t,
                             float* C0, float* C1, int M, int N, int K,
                             const float* bias0, const float* bias1,
                             int do_gelu, int round_out) {
    dim3 grid(N / 64, M / 64, 2);
    gemm_dual_kernel<64, 64, 32, 128, 2, 2><<<grid, 128>>>(
        A0, A1, B0t, B1t, C0, C1, M, N, K, bias0, bias1, do_gelu, round_out);
}

extern "C" void kernel_launch(void* const* d_in, const int* in_sizes, int n_in,
                              void* d_out, int out_size) {
    const float* u      = (const float*)d_in[0];
    const float* cos_y  = (const float*)d_in[1];
    const float* sin_y  = (const float*)d_in[2];
    const float* cos_x  = (const float*)d_in[3];
    const float* sin_x  = (const float*)d_in[4];
    // d_in[5] scalar_cond: unused by reference
    const float* ln1_g  = (const float*)d_in[6];
    const float* ln1_b  = (const float*)d_in[7];
    const float* ln2_g  = (const float*)d_in[8];
    const float* ln2_b  = (const float*)d_in[9];
    const float* Wv     = (const float*)d_in[10];
    const float* Wy_in  = (const float*)d_in[11];
    const float* Wy1    = (const float*)d_in[12];
    const float* by1    = (const float*)d_in[13];
    const float* Wy2    = (const float*)d_in[14];
    const float* by2    = (const float*)d_in[15];
    const float* Wx_in  = (const float*)d_in[16];
    const float* Wx1    = (const float*)d_in[17];
    const float* bx1    = (const float*)d_in[18];
    const float* Wx2    = (const float*)d_in[19];
    const float* bx2    = (const float*)d_in[20];
    const float* Wqk_x  = (const float*)d_in[21];
    const float* Wqk_y  = (const float*)d_in[22];
    const float* Wm     = (const float*)d_in[23];
    const float* bm     = (const float*)d_in[24];
    const float* Wf1    = (const float*)d_in[25];
    const float* bf1    = (const float*)d_in[26];
    const float* Wf2    = (const float*)d_in[27];
    const float* bf2    = (const float*)d_in[28];
    float* out = (float*)d_out;

    cudaFuncSetAttribute(gemm_pipe_kernel<128,128,32,256,2,4,0,1,2,3>,
                         cudaFuncAttributeMaxDynamicSharedMemorySize, BIG3_SMEM_W);
    cudaFuncSetAttribute(gemm_pipe_kernel<128,128,32,256,2,4,1,1,2,3>,
                         cudaFuncAttributeMaxDynamicSharedMemorySize, BIG3_SMEM_W);
    cudaFuncSetAttribute(gemm_pipe_kernel<128,128,32,256,2,4,2,0,2,3>,
                         cudaFuncAttributeMaxDynamicSharedMemorySize, BIG3_SMEM_E);
    cudaFuncSetAttribute(gemm_pipe_kernel<128,128,32,128,2,2,3,0,3,2>,
                         cudaFuncAttributeMaxDynamicSharedMemorySize, BIG2_SMEM_E);

    float *arena, *p_meanx, *p_meany, *p_p2, *p_hsm2, *p_ux, *p_uy, *p_qk2;
    float *p_q2, *p_k2, *p_att2, *p_wr;
    cudaGetSymbolAddress((void**)&arena, g_arena);
    cudaGetSymbolAddress((void**)&p_meanx, g_meanx);
    cudaGetSymbolAddress((void**)&p_meany, g_meany);
    cudaGetSymbolAddress((void**)&p_p2, g_p2);
    cudaGetSymbolAddress((void**)&p_hsm2, g_hsm2);
    cudaGetSymbolAddress((void**)&p_ux, g_ux);
    cudaGetSymbolAddress((void**)&p_uy, g_uy);
    cudaGetSymbolAddress((void**)&p_qk2, g_qk2);
    cudaGetSymbolAddress((void**)&p_q2, g_q2);
    cudaGetSymbolAddress((void**)&p_k2, g_k2);
    cudaGetSymbolAddress((void**)&p_att2, g_att2);
    cudaGetSymbolAddress((void**)&p_wr, g_wr);

    float* p_un    = arena + UN_OFF;
    float* p_vt    = arena + VT_OFF;
    float* p_uphiT = arena + UPHI_OFF;
    float* p_gn    = arena + GN_OFF;
    float* p_u2    = arena + U2_OFF;
    float* p_ln2   = arena + LN2_OFF;
    float* p_hid   = arena + HID_OFF;

    // idx 0: weight round+transpose prep
    round_weights_kernel<<<(int)((W_TOTAL + 255) / 256), 256>>>(
        Wx_in, Wy_in, Wx1, Wy1, Wx2, Wy2, Wqk_x, Wqk_y, Wv, Wm, Wf1, Wf2, p_wr);

    // idx 1: LayerNorm 1 (rounded output)
    ln8_kernel<<<ROWS_ALL / 8, 256>>>(u, ln1_g, ln1_b, p_un, 1e-5f);

    // idx 2: mean over x (rounded)
    mean_over_x_kernel<<<NB * NGR, 256>>>(p_un, p_meany);

    // idx 3: V projection (big GEMM, EPI=1) — ncu sample slot
    gemm_wv(p_un, p_wr + W_V, p_vt, ROWS_ALL, 512, 256);

    // idx 4: mean over y (rounded)
    mean_over_y_kernel<<<NB * NGR, 256>>>(p_un, p_meanx);

    // idx 5-8: pooled reducers + qk projections (x/y batched duals)
    gemm_dual(p_meanx, p_meany, p_wr + W_XIN, p_wr + W_YIN, p_p2, p_p2 + 131072,
              512, 256, 256, nullptr, nullptr, 0, 1);
    gemm_dual(p_p2, p_p2 + 131072, p_wr + W_X1, p_wr + W_Y1, p_hsm2, p_hsm2 + 524288,
              512, 1024, 256, bx1, by1, 1, 1);
    gemm_dual(p_hsm2, p_hsm2 + 524288, p_wr + W_X2, p_wr + W_Y2, p_ux, p_uy,
              512, 256, 1024, bx2, by2, 0, 1);
    gemm_dual(p_ux, p_uy, p_wr + W_QKX, p_wr + W_QKY, p_qk2, p_qk2 + 524288,
              512, 1024, 256, nullptr, nullptr, 0, 0);

    // idx 9: RoPE (x+y)
    rope2_kernel<<<2048, 256>>>(p_qk2, cos_x, sin_x, cos_y, sin_y, p_q2, p_k2);

    // idx 10: scores + softmax (rounded)
    {
        dim3 g(64, 4);
        attn_kernel<<<g, 256>>>(p_q2, p_k2, p_att2);
    }

    // idx 11: einsum1 (k_y) with transpose scatter (rounded)
    gemm_e1(p_att2 + 524288, p_vt, p_uphiT, 128, 8192, 128,
            16384, 1048576, 1048576, NB * HEADS);

    // idx 12: einsum2 (k_x) with fused GroupNorm (rounded)
    gemm_e2(p_att2, p_uphiT, p_gn, 128, 8192, 128,
            16384, 1048576, 0, NB * HEADS);

    // idx 13: u2 = gn @ Wm + bm + u   (NOT rounded — residual carrier)
    gemm_big(p_gn, p_wr + W_M, p_u2, ROWS_ALL, 256, 512, bm, u, 0, 0);

    // idx 14: LN2 (rounded output)
    ln8_kernel<<<ROWS_ALL / 8, 256>>>(p_u2, ln2_g, ln2_b, p_ln2, 1e-5f);

    // idx 15-16: final MLP (hid rounded) + residual (out NOT rounded)
    gemm_big(p_ln2, p_wr + W_F1, p_hid, ROWS_ALL, 1024, 256, bf1, nullptr, 1, 1);
    gemm_big(p_hid, p_wr + W_F2, out, ROWS_ALL, 256, 1024, bf2, p_u2, 0, 0);

    (void)in_sizes; (void)n_in; (void)out_size;
}

// round 17
// speedup vs baseline: 1.1907x; 1.1907x over previous
#include <cuda_runtime.h>
#include <cuda_bf16.h>
#include <math.h>
#include <stdint.h>

// ---------------------------------------------------------------------------
// FABlock2D on GB300. tf32 mma.sync GEMMs, BK=32 2-stage cp.async, ldmatrix
// fragments, reg-capped 256-thread CTAs (16 warps/SM). R17 = R15 (best,
// 1024.5us; R16 3-stage reverted — runtime slot index killed it) + einsum2
// moved to 256 threads with a 4x2 warp grid (WN stays 64 so the GroupNorm
// epilogue is unchanged) -> einsum2 also gets 16 warps/SM.
// ---------------------------------------------------------------------------

#define NB   4
#define NGR  128
#define DIMC 256
#define HEADS 8
#define DH   64
#define ROWS_ALL (NB*NGR*NGR)   // 65536

// ------------------------- scratch (device globals) ------------------------
#define UN_OFF    0L
#define VT_OFF    50331648L
#define UPHI_OFF  0L
#define GN_OFF    33554432L
#define U2_OFF    0L
#define LN2_OFF   16777216L
#define HID_OFF   33554432L
#define ARENA_ELEMS 100663296L

__device__ float g_arena[ARENA_ELEMS];
__device__ float g_meanx[512*256];
__device__ float g_meany[512*256];
__device__ float g_p2   [2*512*256];
__device__ float g_hsm2 [2*512*1024];
__device__ float g_ux   [512*256];
__device__ float g_uy   [512*256];
__device__ float g_qk2  [2*512*1024];
__device__ float g_q2   [2*262144];
__device__ float g_k2   [2*262144];
__device__ float g_att2 [2*524288];   // [0]=x (kx), [1]=y (ky)

// tf32-rounded TRANSPOSED weight copies [N][K]
#define W_XIN  0L
#define W_YIN  65536L
#define W_X1   131072L
#define W_Y1   393216L
#define W_X2   655360L
#define W_Y2   917504L
#define W_QKX  1179648L
#define W_QKY  1441792L
#define W_V    1703936L
#define W_M    1835008L
#define W_F1   1966080L
#define W_F2   2228224L
#define W_TOTAL 2490368L
__device__ float g_wr[W_TOTAL];

// ------------------------------- helpers -----------------------------------
__device__ __forceinline__ float gelu_tanh(float x) {
    float x3 = x * x * x;
    return 0.5f * x * (1.0f + tanhf(0.7978845608028654f * (x + 0.044715f * x3)));
}
__device__ __forceinline__ uint32_t f2tf32(float x) {
    uint32_t r;
    asm("cvt.rna.tf32.f32 %0, %1;" : "=r"(r) : "f"(x));
    return r;
}
__device__ __forceinline__ float tf32r(float x) { return __uint_as_float(f2tf32(x)); }
__device__ __forceinline__ void mma_tf32(float c[4], const uint32_t a[4], const uint32_t b[2]) {
    asm volatile(
        "mma.sync.aligned.m16n8k8.row.col.f32.tf32.tf32.f32 "
        "{%0,%1,%2,%3}, {%4,%5,%6,%7}, {%8,%9}, {%0,%1,%2,%3};\n"
        : "+f"(c[0]), "+f"(c[1]), "+f"(c[2]), "+f"(c[3])
        : "r"(a[0]), "r"(a[1]), "r"(a[2]), "r"(a[3]), "r"(b[0]), "r"(b[1]));
}
__device__ __forceinline__ void cp16(void* dst, const void* src) {
    uint32_t d = (uint32_t)__cvta_generic_to_shared(dst);
    asm volatile("cp.async.ca.shared.global [%0], [%1], 16;\n" :: "r"(d), "l"(src));
}
__device__ __forceinline__ void ldsm4(uint32_t& r0, uint32_t& r1, uint32_t& r2, uint32_t& r3,
                                      uint32_t addr) {
    asm volatile("ldmatrix.sync.aligned.m8n8.x4.shared.b16 {%0,%1,%2,%3}, [%4];"
                 : "=r"(r0), "=r"(r1), "=r"(r2), "=r"(r3) : "r"(addr));
}

// ------------------- weight round+transpose prep (one launch) ---------------
__global__ void round_weights_kernel(
        const float* __restrict__ wxin, const float* __restrict__ wyin,
        const float* __restrict__ wx1,  const float* __restrict__ wy1,
        const float* __restrict__ wx2,  const float* __restrict__ wy2,
        const float* __restrict__ wqkx, const float* __restrict__ wqky,
        const float* __restrict__ wv,   const float* __restrict__ wm,
        const float* __restrict__ wf1,  const float* __restrict__ wf2,
        float* __restrict__ dst) {
    long i = (long)blockIdx.x * 256 + threadIdx.x;
    if (i >= W_TOTAL) return;
    const float* src; long off; int K, N;
    if      (i < W_YIN) { src = wxin; off = W_XIN; K = 256;  N = 256; }
    else if (i < W_X1)  { src = wyin; off = W_YIN; K = 256;  N = 256; }
    else if (i < W_Y1)  { src = wx1;  off = W_X1;  K = 256;  N = 1024; }
    else if (i < W_X2)  { src = wy1;  off = W_Y1;  K = 256;  N = 1024; }
    else if (i < W_Y2)  { src = wx2;  off = W_X2;  K = 1024; N = 256; }
    else if (i < W_QKX) { src = wy2;  off = W_Y2;  K = 1024; N = 256; }
    else if (i < W_QKY) { src = wqkx; off = W_QKX; K = 256;  N = 1024; }
    else if (i < W_V)   { src = wqky; off = W_QKY; K = 256;  N = 1024; }
    else if (i < W_M)   { src = wv;   off = W_V;   K = 256;  N = 512; }
    else if (i < W_F1)  { src = wm;   off = W_M;   K = 512;  N = 256; }
    else if (i < W_F2)  { src = wf1;  off = W_F1;  K = 256;  N = 1024; }
    else                { src = wf2;  off = W_F2;  K = 1024; N = 256; }
    long l = i - off;
    int n = (int)(l / K), k = (int)(l % K);
    dst[i] = tf32r(src[(long)k * N + n]);
}

// --------------------- pipelined tf32 tensor-core GEMM ----------------------
template<int BM, int BN, int BK, int BLDSM>
struct GemmSmem {
    float As[2][BM][BK + 4];
    float Bs[2][BLDSM ? BN : BK][BLDSM ? (BK + 4) : (BN + 8)];
};

template<int BM, int BN, int BK, int THREADS, int WARPS_M, int WARPS_N, int EPI, int BLDSM>
__device__ __forceinline__ void gemm_core(
        const float* __restrict__ A, const float* __restrict__ B, float* __restrict__ C,
        int M, int N, int K, int zb,
        const float* __restrict__ bias, const float* __restrict__ res,
        int do_gelu, int round_out,
        GemmSmem<BM, BN, BK, BLDSM>& sm) {
    constexpr int WM = BM / WARPS_M;
    constexpr int WN = BN / WARPS_N;
    constexpr int MI = WM / 16;
    constexpr int NI = WN / 8;
    constexpr int ITA = (BM * BK / 4) / THREADS;
    constexpr int ITB = (BK * BN / 4) / THREADS;
    constexpr int ASTRIDE = BK + 4;
    constexpr int BSTRIDE = BLDSM ? (BK + 4) : (BN + 8);
    constexpr int A_STG = BM * ASTRIDE;
    constexpr int B_STG = (BLDSM ? BN : BK) * BSTRIDE;

    int tid = threadIdx.x;
    int warp = tid >> 5, lane = tid & 31;
    int wm = warp / WARPS_N, wn = warp % WARPS_N;
    int m0 = blockIdx.y * BM, n0 = blockIdx.x * BN;
    int lg = lane >> 2, lt = lane & 3;
    int lrow = lane & 7, lsel = lane >> 3;

    float c[MI][NI][4] = {};

    auto load_stage = [&](int k0, int s) {
        #pragma unroll
        for (int it = 0; it < ITA; it++) {
            int v = tid + it * THREADS;
            int m = v / (BK / 4), kq = (v % (BK / 4)) * 4;
            cp16(&sm.As[s][m][kq], A + (long)(m0 + m) * K + k0 + kq);
        }
        if (BLDSM) {
            #pragma unroll
            for (int it = 0; it < ITB; it++) {
                int v = tid + it * THREADS;
                int n = v / (BK / 4), kq = (v % (BK / 4)) * 4;
                cp16(&sm.Bs[s][n][kq], B + (long)(n0 + n) * K + k0 + kq);
            }
        } else {
            #pragma unroll
            for (int it = 0; it < ITB; it++) {
                int v = tid + it * THREADS;
                int k = v / (BN / 4), nq = (v % (BN / 4)) * 4;
                cp16(&sm.Bs[s][k][nq], B + (long)(k0 + k) * N + n0 + nq);
            }
        }
    };

    uint32_t As_sm = (uint32_t)__cvta_generic_to_shared(&sm.As[0][0][0]);
    uint32_t Bs_sm = (uint32_t)__cvta_generic_to_shared(&sm.Bs[0][0][0]);
    uint32_t a_off = ((uint32_t)(wm * WM + (lsel & 1) * 8 + lrow) * ASTRIDE
                      + (uint32_t)(lsel >> 1) * 4) * 4u;
    uint32_t b_off = 0;
    if (BLDSM)
        b_off = ((uint32_t)(wn * WN + (lsel >> 1) * 8 + lrow) * BSTRIDE
                 + (uint32_t)(lsel & 1) * 4) * 4u;

    int T = K / BK;
    load_stage(0, 0);
    asm volatile("cp.async.commit_group;\n");
    for (int t = 0; t < T; t++) {
        int cur = t & 1;
        if (t + 1 < T) load_stage((t + 1) * BK, cur ^ 1);
        asm volatile("cp.async.commit_group;\n");
        asm volatile("cp.async.wait_group 1;\n");
        __syncthreads();
        uint32_t a_base = As_sm + (uint32_t)cur * A_STG * 4u + a_off;
        uint32_t b_base = Bs_sm + (uint32_t)cur * B_STG * 4u + b_off;
        #pragma unroll
        for (int ks = 0; ks < BK / 8; ks++) {
            int kb = ks * 8;
            uint32_t af[MI][4], bf[NI][2];
            #pragma unroll
            for (int mi = 0; mi < MI; mi++)
                ldsm4(af[mi][0], af[mi][1], af[mi][2], af[mi][3],
                      a_base + ((uint32_t)(mi * 16 * ASTRIDE + kb)) * 4u);
            if (BLDSM) {
                #pragma unroll
                for (int ni = 0; ni < NI; ni += 2)
                    ldsm4(bf[ni][0], bf[ni][1], bf[ni + 1][0], bf[ni + 1][1],
                          b_base + ((uint32_t)(ni * 8 * BSTRIDE + kb)) * 4u);
            } else {
                #pragma unroll
                for (int ni = 0; ni < NI; ni++) {
                    int nc = wn * WN + ni * 8 + lg;
                    bf[ni][0] = __float_as_uint(sm.Bs[cur][kb + lt][nc]);
                    bf[ni][1] = __float_as_uint(sm.Bs[cur][kb + lt + 4][nc]);
                }
            }
            #pragma unroll
            for (int mi = 0; mi < MI; mi++)
                #pragma unroll
                for (int ni = 0; ni < NI; ni++)
                    mma_tf32(c[mi][ni], af[mi], bf[ni]);
        }
        __syncthreads();
    }

    if (EPI == 3) {
        // GroupNorm epilogue (requires WN == 64: one c-group per warp).
        int b = zb >> 3, h = zb & 7;
        int i_idx = (n0 + wn * WN) >> 6;
        #pragma unroll
        for (int mi = 0; mi < MI; mi++) {
            #pragma unroll
            for (int half = 0; half < 2; half++) {
                float s = 0.f, s2 = 0.f;
                #pragma unroll
                for (int ni = 0; ni < NI; ni++) {
                    float v0 = c[mi][ni][half * 2 + 0];
                    float v1 = c[mi][ni][half * 2 + 1];
                    s += v0 + v1; s2 += v0 * v0 + v1 * v1;
                }
                s  += __shfl_xor_sync(0xffffffffu, s, 1);
                s  += __shfl_xor_sync(0xffffffffu, s, 2);
                s2 += __shfl_xor_sync(0xffffffffu, s2, 1);
                s2 += __shfl_xor_sync(0xffffffffu, s2, 2);
                float mean = s * (1.f / 64.f);
                float var = fmaxf(s2 * (1.f / 64.f) - mean * mean, 0.f);
                float r = rsqrtf(var + 1e-6f);
                int l = wm * WM + mi * 16 + lg + half * 8;
                float* op = C + ((long)((b * 128 + i_idx) * 128 + l)) * 512 + h * 64;
                #pragma unroll
                for (int ni = 0; ni < NI; ni++) {
                    float2 o;
                    o.x = tf32r((c[mi][ni][half * 2 + 0] - mean) * r);
                    o.y = tf32r((c[mi][ni][half * 2 + 1] - mean) * r);
                    *(float2*)(op + ni * 8 + 2 * lt) = o;
                }
            }
        }
        return;
    }
    if (EPI == 2) {
        // einsum1 transpose scatter (generic WN): col -> uphiT[m][(i,c)]
        #pragma unroll
        for (int mi = 0; mi < MI; mi++) {
            #pragma unroll
            for (int half = 0; half < 2; half++) {
                int i_row = m0 + wm * WM + mi * 16 + lg + half * 8;
                #pragma unroll
                for (int ni = 0; ni < NI; ni++) {
                    int col = n0 + wn * WN + ni * 8 + 2 * lt;
                    int m_idx = col >> 6, cc = col & 63;
                    float2 o;
                    o.x = tf32r(c[mi][ni][half * 2 + 0]);
                    o.y = tf32r(c[mi][ni][half * 2 + 1]);
                    *(float2*)(C + (long)m_idx * 8192 + (long)i_row * 64 + cc) = o;
                }
            }
        }
        return;
    }

    #pragma unroll
    for (int mi = 0; mi < MI; mi++) {
        #pragma unroll
        for (int ni = 0; ni < NI; ni++) {
            int col = n0 + wn * WN + ni * 8 + 2 * lt;
            float b0 = 0.f, b1 = 0.f;
            if (EPI == 0 && bias) { b0 = bias[col]; b1 = bias[col + 1]; }
            #pragma unroll
            for (int half = 0; half < 2; half++) {
                long row = m0 + wm * WM + mi * 16 + lg + half * 8;
                float v0 = c[mi][ni][half * 2 + 0] + b0;
                float v1 = c[mi][ni][half * 2 + 1] + b1;
                if (EPI == 0 && do_gelu) { v0 = gelu_tanh(v0); v1 = gelu_tanh(v1); }
                if (EPI == 0 && res) {
                    v0 += res[row * (long)N + col];
                    v1 += res[row * (long)N + col + 1];
                }
                if (EPI == 0 && round_out) { v0 = tf32r(v0); v1 = tf32r(v1); }
                if (EPI == 1) { v0 = tf32r(v0); v1 = tf32r(v1); }
                float2 o; o.x = v0; o.y = v1;
                if (EPI == 1) {
                    int bb = (int)(row >> 14), y = (int)(row >> 7) & 127, x = (int)row & 127;
                    int h = col >> 6, cc = col & 63;
                    long off = ((long)((bb * 8 + h) * 128 + y)) * 8192 + x * 64 + cc;
                    *(float2*)(C + off) = o;
                } else {
                    *(float2*)(C + row * (long)N + col) = o;
                }
            }
        }
    }
}

// MINB enforces the reg budget (256thr, MINB=2 -> 128-reg cap -> 16 warps/SM).
template<int BM, int BN, int BK, int THREADS, int WARPS_M, int WARPS_N, int EPI, int BLDSM,
         int MINB>
__global__ __launch_bounds__(THREADS, MINB) void gemm_pipe_kernel(
        const float* __restrict__ A, const float* __restrict__ B, float* __restrict__ C,
        int M, int N, int K, long sA, long sB, long sC,
        const float* __restrict__ bias, const float* __restrict__ res,
        int do_gelu, int round_out) {
    extern __shared__ __align__(16) float dsm[];
    auto& sm = *reinterpret_cast<GemmSmem<BM, BN, BK, BLDSM>*>(dsm);
    gemm_core<BM, BN, BK, THREADS, WARPS_M, WARPS_N, EPI, BLDSM>(
        A + (long)blockIdx.z * sA, B + (long)blockIdx.z * sB, C + (long)blockIdx.z * sC,
        M, N, K, blockIdx.z, bias, res, do_gelu, round_out, sm);
}

template<int BM, int BN, int BK, int THREADS, int WARPS_M, int WARPS_N>
__global__ __launch_bounds__(THREADS) void gemm_dual_kernel(
        const float* __restrict__ A0, const float* __restrict__ A1,
        const float* __restrict__ B0, const float* __restrict__ B1,
        float* __restrict__ C0, float* __restrict__ C1,
        int M, int N, int K,
        const float* __restrict__ bias0, const float* __restrict__ bias1,
        int do_gelu, int round_out) {
    __shared__ __align__(16) GemmSmem<BM, BN, BK, 1> sm;
    bool z = blockIdx.z != 0;
    gemm_core<BM, BN, BK, THREADS, WARPS_M, WARPS_N, 0, 1>(
        z ? A1 : A0, z ? B1 : B0, z ? C1 : C0, M, N, K, 0,
        z ? bias1 : bias0, nullptr, do_gelu, round_out, sm);
}

#define BIG_SMEM_W  (int)sizeof(GemmSmem<128,128,32,1>)   // ~73.7KB
#define BIG_SMEM_E  (int)sizeof(GemmSmem<128,128,32,0>)   // ~71.7KB

// ----------------------- LayerNorm: warp per row ----------------------------
__global__ void ln8_kernel(const float* __restrict__ x, const float* __restrict__ g,
                           const float* __restrict__ b, float* __restrict__ y, float eps) {
    long row = (long)blockIdx.x * 8 + (threadIdx.x >> 5);
    int lane = threadIdx.x & 31;
    const float* xp = x + row * 256 + lane * 8;
    float4 a = *(const float4*)xp;
    float4 c4 = *(const float4*)(xp + 4);
    float s  = a.x + a.y + a.z + a.w + c4.x + c4.y + c4.z + c4.w;
    float s2 = a.x*a.x + a.y*a.y + a.z*a.z + a.w*a.w
             + c4.x*c4.x + c4.y*c4.y + c4.z*c4.z + c4.w*c4.w;
    #pragma unroll
    for (int o = 16; o; o >>= 1) {
        s  += __shfl_xor_sync(0xffffffffu, s,  o);
        s2 += __shfl_xor_sync(0xffffffffu, s2, o);
    }
    float mean = s * (1.f / 256.f);
    float var  = s2 * (1.f / 256.f) - mean * mean;
    float r = rsqrtf(var + eps);
    const float* gp = g + lane * 8;
    const float* bp = b + lane * 8;
    float* op = y + row * 256 + lane * 8;
    float4 o0, o1;
    o0.x = tf32r((a.x  - mean) * r * gp[0] + bp[0]);
    o0.y = tf32r((a.y  - mean) * r * gp[1] + bp[1]);
    o0.z = tf32r((a.z  - mean) * r * gp[2] + bp[2]);
    o0.w = tf32r((a.w  - mean) * r * gp[3] + bp[3]);
    o1.x = tf32r((c4.x - mean) * r * gp[4] + bp[4]);
    o1.y = tf32r((c4.y - mean) * r * gp[5] + bp[5]);
    o1.z = tf32r((c4.z - mean) * r * gp[6] + bp[6]);
    o1.w = tf32r((c4.w - mean) * r * gp[7] + bp[7]);
    *(float4*)op = o0;
    *(float4*)(op + 4) = o1;
}

// ------------------------- means over x / over y ----------------------------
__global__ void mean_over_x_kernel(const float* __restrict__ un, float* __restrict__ out) {
    int by = blockIdx.x;
    int c = threadIdx.x;
    const float* base = un + (long)by * NGR * DIMC + c;
    float s = 0.f;
    #pragma unroll 4
    for (int x = 0; x < NGR; x++) s += base[(long)x * DIMC];
    out[(long)by * DIMC + c] = tf32r(s * (1.f / (float)NGR));
}
__global__ void mean_over_y_kernel(const float* __restrict__ un, float* __restrict__ out) {
    int bx = blockIdx.x;
    int b = bx >> 7, x = bx & 127;
    int c = threadIdx.x;
    const float* base = un + ((long)b * NGR * NGR + x) * DIMC + c;
    float s = 0.f;
    #pragma unroll 4
    for (int y = 0; y < NGR; y++) s += base[(long)y * NGR * DIMC];
    out[(long)bx * DIMC + c] = tf32r(s * (1.f / (float)NGR));
}

// ------------------------------ RoPE (x+y) ----------------------------------
__global__ void rope2_kernel(const float* __restrict__ qk2,
                             const float* __restrict__ cx, const float* __restrict__ sx,
                             const float* __restrict__ cy, const float* __restrict__ sy,
                             float* __restrict__ q2, float* __restrict__ k2) {
    int idx = blockIdx.x * 256 + threadIdx.x;
    int z = idx >> 18;
    int i = idx & 262143;
    int d = i & 63;
    int n = (i >> 6) & 127;
    int h = (i >> 13) & 7;
    int b = i >> 16;
    const float* P = qk2 + (long)z * 524288 + (long)(b * 128 + n) * 1024;
    const float* cosv = z ? cy : cx;
    const float* sinv = z ? sy : sx;
    float c = cosv[n * 64 + d], s = sinv[n * 64 + d];
    int col = h * 64 + d;
    float t  = P[col];
    float rt = (d < 32) ? -P[col + 32] : P[col - 32];
    q2[idx] = t * c + rt * s;
    float t2  = P[512 + col];
    float rt2 = (d < 32) ? -P[512 + col + 32] : P[512 + col - 32];
    k2[idx] = t2 * c + rt2 * s;
}

// ----------------------- attention scores + softmax -------------------------
__global__ void attn_kernel(const float* __restrict__ q, const float* __restrict__ k,
                            float* __restrict__ attn) {
    __shared__ float qT[64 * 32];
    __shared__ float kT[64 * 128];
    int bh = blockIdx.x;
    int quarter = blockIdx.y;
    const float* qb = q + (long)bh * 8192 + quarter * 2048;
    const float* kb = k + (long)bh * 8192;
    int tid = threadIdx.x;
    for (int t = tid; t < 8192; t += 256) {
        int n = t >> 6, d = t & 63;
        kT[d * 128 + n] = kb[t];
    }
    for (int t = tid; t < 2048; t += 256) {
        int n = t >> 6, d = t & 63;
        qT[d * 32 + n] = qb[t];
    }
    __syncthreads();
    int r = tid >> 3;
    int c0 = (tid & 7) * 2;
    float acc[16] = {};
    #pragma unroll 8
    for (int d = 0; d < 64; d++) {
        float qv = qT[d * 32 + r];
        #pragma unroll
        for (int j = 0; j < 8; j++) {
            acc[2 * j]     += qv * kT[d * 128 + c0 + 16 * j];
            acc[2 * j + 1] += qv * kT[d * 128 + c0 + 1 + 16 * j];
        }
    }
    float mx = -1e30f;
    #pragma unroll
    for (int j = 0; j < 16; j++) { acc[j] *= (1.f / 64.f); mx = fmaxf(mx, acc[j]); }
    #pragma unroll
    for (int o = 1; o < 8; o <<= 1) mx = fmaxf(mx, __shfl_xor_sync(0xffffffffu, mx, o));
    float s = 0.f;
    #pragma unroll
    for (int j = 0; j < 16; j++) { acc[j] = __expf(acc[j] - mx); s += acc[j]; }
    #pragma unroll
    for (int o = 1; o < 8; o <<= 1) s += __shfl_xor_sync(0xffffffffu, s, o);
    float inv = 1.f / s;
    float* op = attn + (long)bh * 16384 + (long)(quarter * 32 + r) * 128;
    #pragma unroll
    for (int j = 0; j < 8; j++) {
        float2 o;
        o.x = tf32r(acc[2 * j] * inv);
        o.y = tf32r(acc[2 * j + 1] * inv);
        *(float2*)(op + c0 + 16 * j) = o;
    }
}

// ------------------------------- host side ----------------------------------
// Big EPI=0/1 GEMMs: 256 threads, 2x4 warps, MINB=2 (128-reg cap -> 16 warps/SM).
static inline void gemm_big(const float* A, const float* Bt, float* C,
                            int M, int N, int K,
                            const float* bias, const float* res, int do_gelu, int round_out) {
    dim3 grid(N / 128, M / 128, 1);
    gemm_pipe_kernel<128, 128, 32, 256, 2, 4, 0, 1, 2><<<grid, 256, BIG_SMEM_W>>>(
        A, Bt, C, M, N, K, 0, 0, 0, bias, res, do_gelu, round_out);
}
static inline void gemm_wv(const float* A, const float* Bt, float* C,
                           int M, int N, int K) {
    dim3 grid(N / 128, M / 128, 1);
    gemm_pipe_kernel<128, 128, 32, 256, 2, 4, 1, 1, 2><<<grid, 256, BIG_SMEM_W>>>(
        A, Bt, C, M, N, K, 0, 0, 0, nullptr, nullptr, 0, 0);
}
static inline void gemm_e1(const float* A, const float* B, float* C,
                           int M, int N, int K, long sA, long sB, long sC, int batch) {
    dim3 grid(N / 128, M / 128, batch);
    gemm_pipe_kernel<128, 128, 32, 256, 2, 4, 2, 0, 2><<<grid, 256, BIG_SMEM_E>>>(
        A, B, C, M, N, K, sA, sB, sC, nullptr, nullptr, 0, 0);
}
// einsum2: 256 threads, 4x2 warp grid (WN=64 preserved for GN), MINB=2.
static inline void gemm_e2(const float* A, const float* B, float* C,
                           int M, int N, int K, long sA, long sB, long sC, int batch) {
    dim3 grid(N / 128, M / 128, batch);
    gemm_pipe_kernel<128, 128, 32, 256, 4, 2, 3, 0, 2><<<grid, 256, BIG_SMEM_E>>>(
        A, B, C, M, N, K, sA, sB, sC, nullptr, nullptr, 0, 0);
}
static inline void gemm_dual(const float* A0, const float* A1,
                             const float* B0t, const float* B1t,
                             float* C0, float* C1, int M, int N, int K,
                             const float* bias0, const float* bias1,
                             int do_gelu, int round_out) {
    dim3 grid(N / 64, M / 64, 2);
    gemm_dual_kernel<64, 64, 32, 128, 2, 2><<<grid, 128>>>(
        A0, A1, B0t, B1t, C0, C1, M, N, K, bias0, bias1, do_gelu, round_out);
}

extern "C" void kernel_launch(void* const* d_in, const int* in_sizes, int n_in,
                              void* d_out, int out_size) {
    const float* u      = (const float*)d_in[0];
    const float* cos_y  = (const float*)d_in[1];
    const float* sin_y  = (const float*)d_in[2];
    const float* cos_x  = (const float*)d_in[3];
    const float* sin_x  = (const float*)d_in[4];
    // d_in[5] scalar_cond: unused by reference
    const float* ln1_g  = (const float*)d_in[6];
    const float* ln1_b  = (const float*)d_in[7];
    const float* ln2_g  = (const float*)d_in[8];
    const float* ln2_b  = (const float*)d_in[9];
    const float* Wv     = (const float*)d_in[10];
    const float* Wy_in  = (const float*)d_in[11];
    const float* Wy1    = (const float*)d_in[12];
    const float* by1    = (const float*)d_in[13];
    const float* Wy2    = (const float*)d_in[14];
    const float* by2    = (const float*)d_in[15];
    const float* Wx_in  = (const float*)d_in[16];
    const float* Wx1    = (const float*)d_in[17];
    const float* bx1    = (const float*)d_in[18];
    const float* Wx2    = (const float*)d_in[19];
    const float* bx2    = (const float*)d_in[20];
    const float* Wqk_x  = (const float*)d_in[21];
    const float* Wqk_y  = (const float*)d_in[22];
    const float* Wm     = (const float*)d_in[23];
    const float* bm     = (const float*)d_in[24];
    const float* Wf1    = (const float*)d_in[25];
    const float* bf1    = (const float*)d_in[26];
    const float* Wf2    = (const float*)d_in[27];
    const float* bf2    = (const float*)d_in[28];
    float* out = (float*)d_out;

    cudaFuncSetAttribute(gemm_pipe_kernel<128,128,32,256,2,4,0,1,2>,
                         cudaFuncAttributeMaxDynamicSharedMemorySize, BIG_SMEM_W);
    cudaFuncSetAttribute(gemm_pipe_kernel<128,128,32,256,2,4,1,1,2>,
                         cudaFuncAttributeMaxDynamicSharedMemorySize, BIG_SMEM_W);
    cudaFuncSetAttribute(gemm_pipe_kernel<128,128,32,256,2,4,2,0,2>,
                         cudaFuncAttributeMaxDynamicSharedMemorySize, BIG_SMEM_E);
    cudaFuncSetAttribute(gemm_pipe_kernel<128,128,32,256,4,2,3,0,2>,
                         cudaFuncAttributeMaxDynamicSharedMemorySize, BIG_SMEM_E);

    float *arena, *p_meanx, *p_meany, *p_p2, *p_hsm2, *p_ux, *p_uy, *p_qk2;
    float *p_q2, *p_k2, *p_att2, *p_wr;
    cudaGetSymbolAddress((void**)&arena, g_arena);
    cudaGetSymbolAddress((void**)&p_meanx, g_meanx);
    cudaGetSymbolAddress((void**)&p_meany, g_meany);
    cudaGetSymbolAddress((void**)&p_p2, g_p2);
    cudaGetSymbolAddress((void**)&p_hsm2, g_hsm2);
    cudaGetSymbolAddress((void**)&p_ux, g_ux);
    cudaGetSymbolAddress((void**)&p_uy, g_uy);
    cudaGetSymbolAddress((void**)&p_qk2, g_qk2);
    cudaGetSymbolAddress((void**)&p_q2, g_q2);
    cudaGetSymbolAddress((void**)&p_k2, g_k2);
    cudaGetSymbolAddress((void**)&p_att2, g_att2);
    cudaGetSymbolAddress((void**)&p_wr, g_wr);

    float* p_un    = arena + UN_OFF;
    float* p_vt    = arena + VT_OFF;
    float* p_uphiT = arena + UPHI_OFF;
    float* p_gn    = arena + GN_OFF;
    float* p_u2    = arena + U2_OFF;
    float* p_ln2   = arena + LN2_OFF;
    float* p_hid   = arena + HID_OFF;

    // idx 0: weight round+transpose prep
    round_weights_kernel<<<(int)((W_TOTAL + 255) / 256), 256>>>(
        Wx_in, Wy_in, Wx1, Wy1, Wx2, Wy2, Wqk_x, Wqk_y, Wv, Wm, Wf1, Wf2, p_wr);

    // idx 1: LayerNorm 1 (rounded output)
    ln8_kernel<<<ROWS_ALL / 8, 256>>>(u, ln1_g, ln1_b, p_un, 1e-5f);

    // idx 2: mean over x (rounded)
    mean_over_x_kernel<<<NB * NGR, 256>>>(p_un, p_meany);

    // idx 3: V projection (big GEMM, EPI=1) — ncu sample slot
    gemm_wv(p_un, p_wr + W_V, p_vt, ROWS_ALL, 512, 256);

    // idx 4: mean over y (rounded)
    mean_over_y_kernel<<<NB * NGR, 256>>>(p_un, p_meanx);

    // idx 5-8: pooled reducers + qk projections (x/y batched duals)
    gemm_dual(p_meanx, p_meany, p_wr + W_XIN, p_wr + W_YIN, p_p2, p_p2 + 131072,
              512, 256, 256, nullptr, nullptr, 0, 1);
    gemm_dual(p_p2, p_p2 + 131072, p_wr + W_X1, p_wr + W_Y1, p_hsm2, p_hsm2 + 524288,
              512, 1024, 256, bx1, by1, 1, 1);
    gemm_dual(p_hsm2, p_hsm2 + 524288, p_wr + W_X2, p_wr + W_Y2, p_ux, p_uy,
              512, 256, 1024, bx2, by2, 0, 1);
    gemm_dual(p_ux, p_uy, p_wr + W_QKX, p_wr + W_QKY, p_qk2, p_qk2 + 524288,
              512, 1024, 256, nullptr, nullptr, 0, 0);

    // idx 9: RoPE (x+y)
    rope2_kernel<<<2048, 256>>>(p_qk2, cos_x, sin_x, cos_y, sin_y, p_q2, p_k2);

    // idx 10: scores + softmax (rounded)
    {
        dim3 g(64, 4);
        attn_kernel<<<g, 256>>>(p_q2, p_k2, p_att2);
    }

    // idx 11: einsum1 (k_y) with transpose scatter (rounded)
    gemm_e1(p_att2 + 524288, p_vt, p_uphiT, 128, 8192, 128,
            16384, 1048576, 1048576, NB * HEADS);

    // idx 12: einsum2 (k_x) with fused GroupNorm (rounded)
    gemm_e2(p_att2, p_uphiT, p_gn, 128, 8192, 128,
            16384, 1048576, 0, NB * HEADS);

    // idx 13: u2 = gn @ Wm + bm + u   (NOT rounded — residual carrier)
    gemm_big(p_gn, p_wr + W_M, p_u2, ROWS_ALL, 256, 512, bm, u, 0, 0);

    // idx 14: LN2 (rounded output)
    ln8_kernel<<<ROWS_ALL / 8, 256>>>(p_u2, ln2_g, ln2_b, p_ln2, 1e-5f);

    // idx 15-16: final MLP (hid rounded) + residual (out NOT rounded)
    gemm_big(p_ln2, p_wr + W_F1, p_hid, ROWS_ALL, 1024, 256, bf1, nullptr, 1, 1);
    gemm_big(p_hid, p_wr + W_F2, out, ROWS_ALL, 256, 1024, bf2, p_u2, 0, 0);

    (void)in_sizes; (void)n_in; (void)out_size;
}